// round 16
// baseline (speedup 1.0000x reference)
#include <cuda_runtime.h>
#include <cuda_bf16.h>
#include <math.h>
#include <stdint.h>

// Problem constants
#define SEQ  2048
#define DIM  1024
#define NH   16
#define HD   64
#define KS   2048      // compact split storage width ([H|L])
#define NCH  48        // logical K chunks of 64 (3 x 1024 / 64)

// Scratch (device globals; allocations are forbidden)
__device__ float g_q[SEQ * DIM];
__device__ float g_part[SEQ * DIM];               // split-K partial for Wout
__device__ float g_cos[SEQ * 32];
__device__ float g_sin[SEQ * 32];
__device__ __nv_bfloat16 g_kh[SEQ * DIM], g_kl[SEQ * DIM];
__device__ __nv_bfloat16 g_vh[SEQ * DIM], g_vl[SEQ * DIM];
__device__ __nv_bfloat16 g_abig[SEQ * KS];        // [Ah|Al] for x / att
__device__ __nv_bfloat16 g_wbig[4][DIM * KS];     // [Wh|Wl] per weight

// ===========================================================================
// Helpers (sm_80+ generic)
// ===========================================================================
__device__ __forceinline__ uint32_t smem_u32(const void* p) {
    uint32_t a;
    asm("{ .reg .u64 t; cvta.to.shared.u64 t, %1; cvt.u32.u64 %0, t; }"
        : "=r"(a) : "l"(p));
    return a;
}
__device__ __forceinline__ void ldsm_x4(uint32_t* r, uint32_t addr) {
    asm volatile("ldmatrix.sync.aligned.m8n8.x4.shared.b16 {%0,%1,%2,%3}, [%4];"
                 : "=r"(r[0]), "=r"(r[1]), "=r"(r[2]), "=r"(r[3]) : "r"(addr));
}
__device__ __forceinline__ void ldsm_x4_t(uint32_t* r, uint32_t addr) {
    asm volatile("ldmatrix.sync.aligned.m8n8.x4.trans.shared.b16 {%0,%1,%2,%3}, [%4];"
                 : "=r"(r[0]), "=r"(r[1]), "=r"(r[2]), "=r"(r[3]) : "r"(addr));
}
__device__ __forceinline__ void mma16816(float* d, const uint32_t* a, const uint32_t* b) {
    asm volatile("mma.sync.aligned.m16n8k16.row.col.f32.bf16.bf16.f32 "
                 "{%0,%1,%2,%3}, {%4,%5,%6,%7}, {%8,%9}, {%0,%1,%2,%3};"
                 : "+f"(d[0]), "+f"(d[1]), "+f"(d[2]), "+f"(d[3])
                 : "r"(a[0]), "r"(a[1]), "r"(a[2]), "r"(a[3]),
                   "r"(b[0]), "r"(b[1]));
}
__device__ __forceinline__ void cp_async16(uint32_t dst, const void* src) {
    asm volatile("cp.async.cg.shared.global [%0], [%1], 16;" :: "r"(dst), "l"(src));
}
#define CP_COMMIT() asm volatile("cp.async.commit_group;" ::: "memory")
#define CP_WAIT(n)  asm volatile("cp.async.wait_group %0;" :: "n"(n) : "memory")

__device__ __forceinline__ uint32_t sw128(uint32_t off) {
    return off ^ ((off >> 3) & 0x70);
}
// Packed split: hi = bf16x2(x,y); residual lo via shift/mask-recovered hi floats.
// Bit-identical to the scalar __float2bfloat16 path for finite inputs.
__device__ __forceinline__ uint32_t pack_split(float x, float y, uint32_t* lo) {
    uint32_t hi;
    asm("cvt.rn.bf16x2.f32 %0, %1, %2;" : "=r"(hi) : "f"(y), "f"(x));
    float hfx = __uint_as_float(hi << 16);
    float hfy = __uint_as_float(hi & 0xFFFF0000u);
    float rx = x - hfx, ry = y - hfy;
    uint32_t l;
    asm("cvt.rn.bf16x2.f32 %0, %1, %2;" : "=r"(l) : "f"(ry), "f"(rx));
    *lo = l;
    return hi;
}

// ===========================================================================
// Fused prologue: rope table + x split + 4 weight splits + v1 tail copy.
// Block ranges: [0,256) rope | [256,1280) x | [1280,3328) weights | rest copy.
// ===========================================================================
__global__ __launch_bounds__(256) void prep_kernel(const float* __restrict__ x,
                                                   const float* __restrict__ Wq,
                                                   const float* __restrict__ Wk,
                                                   const float* __restrict__ Wv,
                                                   const float* __restrict__ Wo,
                                                   const float4* __restrict__ v1_4,
                                                   float4* __restrict__ out_tail) {
    int b = blockIdx.x, tid = threadIdx.x;
    if (b < 256) {                              // RoPE table
        int idx = b * 256 + tid;
        int t = idx >> 5, i = idx & 31;
        double p = pow(10000.0, (double)i / 32.0);
        float invf = 1.0f / (float)p;
        float f = (float)t * invf;
        double fd = (double)f;
        g_cos[t * 32 + i] = (float)cos(fd);
        g_sin[t * 32 + i] = (float)sin(fd);
    } else if (b < 1280) {                      // x -> abig [H|L]
        int base = (b - 256) * 512;
#pragma unroll
        for (int i = 0; i < 2; i++) {
            int idx = base + i * 256 + tid;     // float4 index
            int r = idx >> 8, c4 = idx & 255;
            float4 xv = *(const float4*)&x[(size_t)idx * 4];
            uint32_t l0, l1;
            uint32_t h0 = pack_split(xv.x, xv.y, &l0);
            uint32_t h1 = pack_split(xv.z, xv.w, &l1);
            size_t d = (size_t)r * KS + c4 * 4;
            *(uint2*)&g_abig[d] = make_uint2(h0, h1);
            *(uint2*)&g_abig[d + 1024] = make_uint2(l0, l1);
        }
    } else if (b < 3328) {                      // weights -> wbig [H|L]
        int j = b - 1280;
        int wsel = j >> 9;
        const float* src = (wsel == 0) ? Wq : (wsel == 1) ? Wk : (wsel == 2) ? Wv : Wo;
        __nv_bfloat16* d = g_wbig[wsel];
        int base = (j & 511) * 512;
#pragma unroll
        for (int i = 0; i < 2; i++) {
            int idx = base + i * 256 + tid;
            int r = idx >> 8, c4 = idx & 255;
            float4 xv = *(const float4*)&src[(size_t)idx * 4];
            uint32_t l0, l1;
            uint32_t h0 = pack_split(xv.x, xv.y, &l0);
            uint32_t h1 = pack_split(xv.z, xv.w, &l1);
            size_t db = (size_t)r * KS + c4 * 4;
            *(uint2*)&d[db] = make_uint2(h0, h1);
            *(uint2*)&d[db + 1024] = make_uint2(l0, l1);
        }
    } else {                                    // v1 passthrough tail (2 f4/thread)
        int i0 = (b - 3328) * 512 + tid;
        out_tail[i0] = v1_4[i0];
        out_tail[i0 + 256] = v1_4[i0 + 256];
    }
}

// ===========================================================================
// HMMA NT GEMM, 3-term split via chunk remap. CTA 64x128, 4 warps (32x64),
// 2-stage cp.async, 4 CTAs/SM. FUSE=1: QKV with fused epilogue, all 48
// chunks, z in {0,1,2} selects output. FUSE=0: Wout, split-K2 — z in {0,1}
// selects chunk half and destination (C0=out, C1=partial).
// ===========================================================================
#define TM 64
#define TN 128
#define ASZ (TM * 128)             // 8 KB
#define BSZ (TN * 128)             // 16 KB
#define SSTG (ASZ + BSZ)           // 24 KB per stage
#define GSMEM (2 * SSTG)           // 48 KB

__device__ __forceinline__ void g_load_chunk(uint32_t sb, int st,
                                             const char* Ag, const char* Bg,
                                             int c, int tid) {
    uint32_t ab = sb + st * SSTG;
    uint32_t bb = ab + ASZ;
    int ca = (c < 16) ? c : c - 16;
    int cb = (c < 32) ? c : c - 32;
    size_t aoff = (size_t)ca * 128;
    size_t boff = (size_t)cb * 128;
#pragma unroll
    for (int i = 0; i < 4; i++) {              // A: 64 rows x 8 segs
        int u = tid + i * 128;
        int row = u >> 3, seg = u & 7;
        uint32_t off = row * 128 + seg * 16;
        cp_async16(ab + sw128(off), Ag + (size_t)row * (KS * 2) + aoff + seg * 16);
    }
#pragma unroll
    for (int i = 0; i < 8; i++) {              // B: 128 rows x 8 segs
        int u = tid + i * 128;
        int row = u >> 3, seg = u & 7;
        uint32_t off = row * 128 + seg * 16;
        cp_async16(bb + sw128(off), Bg + (size_t)row * (KS * 2) + boff + seg * 16);
    }
}

template <int FUSE>
__global__ __launch_bounds__(128, 4) void gemm_hmma3(const __nv_bfloat16* __restrict__ A,
                                                     const __nv_bfloat16* __restrict__ Bbase,
                                                     float* __restrict__ C0,
                                                     float* __restrict__ C1,
                                                     const float* __restrict__ v1,
                                                     const float* __restrict__ lam_p) {
    extern __shared__ __align__(128) char smem[];
    uint32_t sb = smem_u32(smem);
    int z = blockIdx.z;
    const __nv_bfloat16* B = Bbase + (FUSE ? (size_t)z * DIM * KS : 0);

    int tid = threadIdx.x;
    int wid = tid >> 5, lane = tid & 31;
    int wm = wid & 1, wn = wid >> 1;            // warp tile (wm*32, wn*64)
    int bm = blockIdx.y * TM, bn = blockIdx.x * TN;

    const char* Ag = (const char*)(A + (size_t)bm * KS);
    const char* Bg = (const char*)(B + (size_t)bn * KS);

    int cbeg = FUSE ? 0 : z * (NCH / 2);
    int cend = FUSE ? NCH : (z + 1) * (NCH / 2);

    float acc[2][8][4];
#pragma unroll
    for (int mt = 0; mt < 2; mt++)
#pragma unroll
        for (int nt = 0; nt < 8; nt++)
#pragma unroll
            for (int r = 0; r < 4; r++) acc[mt][nt][r] = 0.f;

    g_load_chunk(sb, 0, Ag, Bg, cbeg, tid);
    CP_COMMIT();

    int a_row = wm * 32 + (lane & 15);
    int a_kb  = (lane >> 4) * 16;
    int b_row = wn * 64 + (lane & 7) + ((lane >> 4) << 3);
    int b_kb  = ((lane >> 3) & 1) * 16;

    int st = 0;
    for (int c = cbeg; c < cend; c++) {
        CP_WAIT(0);                      // chunk c resident
        __syncthreads();                 // all warps finished reading other buffer
        if (c + 1 < cend) {
            g_load_chunk(sb, st ^ 1, Ag, Bg, c + 1, tid);
            CP_COMMIT();
        }

        uint32_t abase = sb + st * SSTG;
        uint32_t bbase = abase + ASZ;
#pragma unroll
        for (int ks = 0; ks < 4; ks++) {
            uint32_t af[2][4];
#pragma unroll
            for (int mt = 0; mt < 2; mt++) {
                uint32_t off = (a_row + mt * 16) * 128 + ks * 32 + a_kb;
                ldsm_x4(af[mt], abase + sw128(off));
            }
            uint32_t bfr[4][4];
#pragma unroll
            for (int bt = 0; bt < 4; bt++) {
                uint32_t off = (b_row + bt * 16) * 128 + ks * 32 + b_kb;
                ldsm_x4(bfr[bt], bbase + sw128(off));
            }
#pragma unroll
            for (int mt = 0; mt < 2; mt++)
#pragma unroll
                for (int nt = 0; nt < 8; nt++)
                    mma16816(acc[mt][nt], af[mt], &bfr[nt >> 1][(nt & 1) * 2]);
        }
        st ^= 1;
    }

    int gq = lane >> 2, cp = (lane & 3) * 2;

    if (FUSE == 0) {
        // Plain epilogue; z selects out vs partial
        float* C = z ? C1 : C0;
#pragma unroll
        for (int mt = 0; mt < 2; mt++) {
#pragma unroll
            for (int nt = 0; nt < 8; nt++) {
                int row = bm + wm * 32 + mt * 16 + gq;
                int col = bn + wn * 64 + nt * 8 + cp;
                *(float2*)&C[(size_t)row * DIM + col] =
                    make_float2(acc[mt][nt][0], acc[mt][nt][1]);
                *(float2*)&C[(size_t)(row + 8) * DIM + col] =
                    make_float2(acc[mt][nt][2], acc[mt][nt][3]);
            }
        }
        return;
    }

    // Fused QKV epilogue. Warp covers one head's 64 cols (colbase..+63).
    const float eps = 1.1920928955078125e-07f;
    int colbase = bn + wn * 64;

    if (z == 2) {
        float lamv = *lam_p;
#pragma unroll
        for (int mt = 0; mt < 2; mt++) {
#pragma unroll
            for (int half = 0; half < 2; half++) {
                int row = bm + wm * 32 + mt * 16 + gq + half * 8;
#pragma unroll
                for (int nt = 0; nt < 8; nt++) {
                    int col = colbase + nt * 8 + cp;
                    float2 w = *(const float2*)&v1[(size_t)row * DIM + col];
                    float a = (1.f - lamv) * acc[mt][nt][half * 2]     + lamv * w.x;
                    float b = (1.f - lamv) * acc[mt][nt][half * 2 + 1] + lamv * w.y;
                    uint32_t lo, hi = pack_split(a, b, &lo);
                    size_t o = (size_t)row * DIM + col;
                    *(uint32_t*)&g_vh[o] = hi;
                    *(uint32_t*)&g_vl[o] = lo;
                }
            }
        }
        return;
    }

    // z == 0 (Q) or z == 1 (K): rmsnorm (quad reduce) + rope
#pragma unroll
    for (int mt = 0; mt < 2; mt++) {
#pragma unroll
        for (int half = 0; half < 2; half++) {
            int row = bm + wm * 32 + mt * 16 + gq + half * 8;
            float ss = 0.f;
#pragma unroll
            for (int nt = 0; nt < 8; nt++) {
                float a = acc[mt][nt][half * 2], b = acc[mt][nt][half * 2 + 1];
                ss += a * a + b * b;
            }
            ss += __shfl_xor_sync(0xffffffffu, ss, 1);
            ss += __shfl_xor_sync(0xffffffffu, ss, 2);
            float mean = ss * (1.f / 64.f) + eps;
            float rn = rsqrtf(mean);
            rn = rn * (1.5f - 0.5f * mean * rn * rn);
#pragma unroll
            for (int nt = 0; nt < 4; nt++) {
                int d0 = nt * 8 + cp;                 // < 32
                float c0 = g_cos[row * 32 + d0],  s0 = g_sin[row * 32 + d0];
                float c1 = g_cos[row * 32 + d0 + 1], s1 = g_sin[row * 32 + d0 + 1];
                float a0 = acc[mt][nt][half * 2] * rn;
                float a1 = acc[mt][nt][half * 2 + 1] * rn;
                float b0 = acc[mt][nt + 4][half * 2] * rn;
                float b1 = acc[mt][nt + 4][half * 2 + 1] * rn;
                float o0 = a0 * c0 + b0 * s0, o1 = a1 * c1 + b1 * s1;
                float p0 = -a0 * s0 + b0 * c0, p1 = -a1 * s1 + b1 * c1;
                size_t ob = (size_t)row * DIM + colbase + d0;
                if (z == 0) {
                    *(float2*)&g_q[ob]      = make_float2(o0, o1);
                    *(float2*)&g_q[ob + 32] = make_float2(p0, p1);
                } else {
                    uint32_t lo, hi = pack_split(o0, o1, &lo);
                    *(uint32_t*)&g_kh[ob] = hi;
                    *(uint32_t*)&g_kl[ob] = lo;
                    hi = pack_split(p0, p1, &lo);
                    *(uint32_t*)&g_kh[ob + 32] = hi;
                    *(uint32_t*)&g_kl[ob + 32] = lo;
                }
            }
        }
    }
}

// Deterministic split-K reduction: out += part
__global__ __launch_bounds__(256) void reduce_kernel(float4* __restrict__ out,
                                                     const float4* __restrict__ part) {
    int i = blockIdx.x * 256 + threadIdx.x;
    float4 a = out[i], b = part[i];
    a.x += b.x; a.y += b.y; a.z += b.z; a.w += b.w;
    out[i] = a;
}

// ===========================================================================
// Flash attention v5: panel-factored split-term loops. (unchanged, proven)
// ===========================================================================
#define FSTG 32768          // 4 panels x 8 KB per stage
#define FSMEM (2 * FSTG)

__device__ __forceinline__ void f_load_kv(uint32_t sb, int s, int kt,
                                          int h, int tid) {
    const __nv_bfloat16* srcs[4] = {g_kh, g_kl, g_vh, g_vl};
#pragma unroll
    for (int p = 0; p < 4; p++) {
        uint32_t pb = sb + s * FSTG + p * 8192;
        const char* gp = (const char*)(srcs[p] + (size_t)(kt * 64) * DIM + h * HD);
#pragma unroll
        for (int i = 0; i < 2; i++) {
            int u = tid + i * 256;
            int r = u >> 3, seg = u & 7;
            uint32_t off = r * 128 + seg * 16;
            cp_async16(pb + sw128(off), gp + (size_t)r * (DIM * 2) + seg * 16);
        }
    }
}

__global__ __launch_bounds__(256, 1) void flash_hmma(__nv_bfloat16* __restrict__ abig) {
    extern __shared__ __align__(128) char fsm[];
    uint32_t sb = smem_u32(fsm);

    int h  = blockIdx.x;
    int qt = 15 - (int)blockIdx.y;          // LPT: heavy tiles first
    int q0 = qt * 128;
    int tid = threadIdx.x, w = tid >> 5, lane = tid & 31;
    int g = lane >> 2, t4 = lane & 3;

    // Q fragments: scale by 0.125, split hi/lo
    uint32_t aqh[4][4], aql[4][4];
    {
        int row0 = q0 + w * 16 + g;
#pragma unroll
        for (int ks = 0; ks < 4; ks++) {
            int cb = h * HD + ks * 16 + 2 * t4;
            float2 f[4];
            f[0] = *(const float2*)&g_q[(size_t)row0 * DIM + cb];
            f[1] = *(const float2*)&g_q[(size_t)(row0 + 8) * DIM + cb];
            f[2] = *(const float2*)&g_q[(size_t)row0 * DIM + cb + 8];
            f[3] = *(const float2*)&g_q[(size_t)(row0 + 8) * DIM + cb + 8];
#pragma unroll
            for (int r = 0; r < 4; r++)
                aqh[ks][r] = pack_split(f[r].x * 0.125f, f[r].y * 0.125f, &aql[ks][r]);
        }
    }

    float m0 = -1e30f, m1 = -1e30f, l0 = 0.f, l1 = 0.f;
    float o[8][4];
#pragma unroll
    for (int nt = 0; nt < 8; nt++)
#pragma unroll
        for (int r = 0; r < 4; r++) o[nt][r] = 0.f;

    int nbr = (lane & 7) + ((lane >> 4) << 3);
    int nbk = ((lane >> 3) & 1) * 16;
    int tvr = (lane & 7) + 8 * ((lane >> 3) & 1);
    int tvc = 16 * (lane >> 4);

    f_load_kv(sb, 0, 0, h, tid);
    CP_COMMIT();

    int nkt = 2 * qt + 2;
    for (int kt = 0; kt < nkt; kt++) {
        int buf = kt & 1;
        if (kt + 1 < nkt) {
            f_load_kv(sb, buf ^ 1, kt + 1, h, tid);
            CP_COMMIT();
            CP_WAIT(1);
        } else {
            CP_WAIT(0);
        }
        __syncthreads();

        if (kt * 64 <= q0 + w * 16 + 15) {
            uint32_t stg = sb + buf * FSTG;

            float s[8][4];
#pragma unroll
            for (int nt = 0; nt < 8; nt++)
#pragma unroll
                for (int r = 0; r < 4; r++) s[nt][r] = 0.f;

            // --- QK pass 1: K-hi panel, terms qh.KH and ql.KH ---
#pragma unroll
            for (int ks = 0; ks < 4; ks++) {
                uint32_t bfr[4][4];
#pragma unroll
                for (int bt = 0; bt < 4; bt++) {
                    uint32_t off = sw128((uint32_t)((nbr + bt * 16) * 128 + ks * 32 + nbk));
                    ldsm_x4(bfr[bt], stg + off);
                }
#pragma unroll
                for (int nt = 0; nt < 8; nt++)
                    mma16816(s[nt], aqh[ks], &bfr[nt >> 1][(nt & 1) * 2]);
#pragma unroll
                for (int nt = 0; nt < 8; nt++)
                    mma16816(s[nt], aql[ks], &bfr[nt >> 1][(nt & 1) * 2]);
            }
            // --- QK pass 2: K-lo panel, term qh.KL ---
#pragma unroll
            for (int ks = 0; ks < 4; ks++) {
                uint32_t bfr[4][4];
#pragma unroll
                for (int bt = 0; bt < 4; bt++) {
                    uint32_t off = sw128((uint32_t)((nbr + bt * 16) * 128 + ks * 32 + nbk));
                    ldsm_x4(bfr[bt], stg + 8192 + off);
                }
#pragma unroll
                for (int nt = 0; nt < 8; nt++)
                    mma16816(s[nt], aqh[ks], &bfr[nt >> 1][(nt & 1) * 2]);
            }

            if (kt >= 2 * qt) {
                int r0 = q0 + w * 16 + g, r1 = r0 + 8;
                int c0 = kt * 64 + 2 * t4;
#pragma unroll
                for (int nt = 0; nt < 8; nt++) {
                    int c = c0 + nt * 8;
                    if (c     > r0) s[nt][0] = -1e30f;
                    if (c + 1 > r0) s[nt][1] = -1e30f;
                    if (c     > r1) s[nt][2] = -1e30f;
                    if (c + 1 > r1) s[nt][3] = -1e30f;
                }
            }

            float mx0 = -1e30f, mx1 = -1e30f;
#pragma unroll
            for (int nt = 0; nt < 8; nt++) {
                mx0 = fmaxf(mx0, fmaxf(s[nt][0], s[nt][1]));
                mx1 = fmaxf(mx1, fmaxf(s[nt][2], s[nt][3]));
            }
            mx0 = fmaxf(mx0, __shfl_xor_sync(0xffffffffu, mx0, 1));
            mx0 = fmaxf(mx0, __shfl_xor_sync(0xffffffffu, mx0, 2));
            mx1 = fmaxf(mx1, __shfl_xor_sync(0xffffffffu, mx1, 1));
            mx1 = fmaxf(mx1, __shfl_xor_sync(0xffffffffu, mx1, 2));
            float mn0 = fmaxf(m0, mx0), mn1 = fmaxf(m1, mx1);
            float al0 = __expf(m0 - mn0), al1 = __expf(m1 - mn1);
            float sum0 = 0.f, sum1 = 0.f;
#pragma unroll
            for (int nt = 0; nt < 8; nt++) {
                s[nt][0] = __expf(s[nt][0] - mn0);
                s[nt][1] = __expf(s[nt][1] - mn0);
                s[nt][2] = __expf(s[nt][2] - mn1);
                s[nt][3] = __expf(s[nt][3] - mn1);
                sum0 += s[nt][0] + s[nt][1];
                sum1 += s[nt][2] + s[nt][3];
            }
            sum0 += __shfl_xor_sync(0xffffffffu, sum0, 1);
            sum0 += __shfl_xor_sync(0xffffffffu, sum0, 2);
            sum1 += __shfl_xor_sync(0xffffffffu, sum1, 1);
            sum1 += __shfl_xor_sync(0xffffffffu, sum1, 2);
            l0 = l0 * al0 + sum0;  m0 = mn0;
            l1 = l1 * al1 + sum1;  m1 = mn1;
#pragma unroll
            for (int nt = 0; nt < 8; nt++) {
                o[nt][0] *= al0; o[nt][1] *= al0;
                o[nt][2] *= al1; o[nt][3] *= al1;
            }

            uint32_t ph[4][4], pl[4][4];
#pragma unroll
            for (int j = 0; j < 4; j++) {
                int u0 = 2 * j, u1 = 2 * j + 1;
                ph[j][0] = pack_split(s[u0][0], s[u0][1], &pl[j][0]);
                ph[j][1] = pack_split(s[u0][2], s[u0][3], &pl[j][1]);
                ph[j][2] = pack_split(s[u1][0], s[u1][1], &pl[j][2]);
                ph[j][3] = pack_split(s[u1][2], s[u1][3], &pl[j][3]);
            }

            // --- PV pass 1: V-hi panel, terms ph.VH and pl.VH ---
#pragma unroll
            for (int j = 0; j < 4; j++) {
                uint32_t bv[4][4];
#pragma unroll
                for (int bt = 0; bt < 4; bt++) {
                    uint32_t off = sw128((uint32_t)((j * 16 + tvr) * 128 + bt * 32 + tvc));
                    ldsm_x4_t(bv[bt], stg + 16384 + off);
                }
#pragma unroll
                for (int nt = 0; nt < 8; nt++)
                    mma16816(o[nt], ph[j], &bv[nt >> 1][(nt & 1) * 2]);
#pragma unroll
                for (int nt = 0; nt < 8; nt++)
                    mma16816(o[nt], pl[j], &bv[nt >> 1][(nt & 1) * 2]);
            }
            // --- PV pass 2: V-lo panel, term ph.VL ---
#pragma unroll
            for (int j = 0; j < 4; j++) {
                uint32_t bv[4][4];
#pragma unroll
                for (int bt = 0; bt < 4; bt++) {
                    uint32_t off = sw128((uint32_t)((j * 16 + tvr) * 128 + bt * 32 + tvc));
                    ldsm_x4_t(bv[bt], stg + 24576 + off);
                }
#pragma unroll
                for (int nt = 0; nt < 8; nt++)
                    mma16816(o[nt], ph[j], &bv[nt >> 1][(nt & 1) * 2]);
            }
        }
        __syncthreads();
    }

    // Epilogue: normalize, split to [H|L] directly into abig
    float i0 = 1.f / l0, i1 = 1.f / l1;
    int row0 = q0 + w * 16 + g;
#pragma unroll
    for (int nt = 0; nt < 8; nt++) {
        int col = h * HD + nt * 8 + 2 * t4;
        size_t b0 = (size_t)row0 * KS + col;
        size_t b1 = (size_t)(row0 + 8) * KS + col;
        uint32_t lo, hi;
        hi = pack_split(o[nt][0] * i0, o[nt][1] * i0, &lo);
        *(uint32_t*)&abig[b0] = hi;
        *(uint32_t*)&abig[b0 + 1024] = lo;
        hi = pack_split(o[nt][2] * i1, o[nt][3] * i1, &lo);
        *(uint32_t*)&abig[b1] = hi;
        *(uint32_t*)&abig[b1 + 1024] = lo;
    }
}

// ===========================================================================
extern "C" void kernel_launch(void* const* d_in, const int* in_sizes, int n_in,
                              void* d_out, int out_size) {
    const float* x    = (const float*)d_in[0];
    const float* v1   = (const float*)d_in[1];
    const float* Wq   = (const float*)d_in[2];
    const float* Wk   = (const float*)d_in[3];
    const float* Wv   = (const float*)d_in[4];
    const float* Wout = (const float*)d_in[5];
    const float* lam  = (const float*)d_in[6];
    float* out = (float*)d_out;

    __nv_bfloat16 *abig, *wbig;
    float* part;
    cudaGetSymbolAddress((void**)&abig, g_abig);
    cudaGetSymbolAddress((void**)&wbig, g_wbig);
    cudaGetSymbolAddress((void**)&part, g_part);

    static bool attr_set = false;
    if (!attr_set) {
        cudaFuncSetAttribute(gemm_hmma3<0>, cudaFuncAttributeMaxDynamicSharedMemorySize, GSMEM);
        cudaFuncSetAttribute(gemm_hmma3<1>, cudaFuncAttributeMaxDynamicSharedMemorySize, GSMEM);
        cudaFuncSetAttribute(flash_hmma, cudaFuncAttributeMaxDynamicSharedMemorySize, FSMEM);
        attr_set = true;
    }

    // Fused prologue: rope + splits + v1 tail copy
    int copy_blocks = (out_size >= 2 * SEQ * DIM) ? (SEQ * DIM) / 2048 : 0;
    prep_kernel<<<3328 + copy_blocks, 256>>>(x, Wq, Wk, Wv, Wout,
                                             (const float4*)v1,
                                             (float4*)(out + SEQ * DIM));

    // Fused QKV projections + rmsnorm/rope/blend epilogue
    gemm_hmma3<1><<<dim3(DIM / TN, SEQ / TM, 3), 128, GSMEM>>>(
        abig, wbig, nullptr, nullptr, v1, lam);

    flash_hmma<<<dim3(NH, SEQ / 128), 256, FSMEM>>>(abig);

    // Output projection, split-K2: z=0 -> out, z=1 -> partial; then reduce
    gemm_hmma3<0><<<dim3(DIM / TN, SEQ / TM, 2), 128, GSMEM>>>(
        abig, wbig + 3 * (size_t)DIM * KS, out, part, nullptr, nullptr);
    reduce_kernel<<<(SEQ * DIM) / 1024, 256>>>((float4*)out, (const float4*)part);
}

// round 17
// speedup vs baseline: 1.0343x; 1.0343x over previous
#include <cuda_runtime.h>
#include <cuda_bf16.h>
#include <math.h>
#include <stdint.h>

// Problem constants
#define SEQ  2048
#define DIM  1024
#define NH   16
#define HD   64
#define KS   2048      // compact split storage width ([H|L])
#define NCH  48        // logical K chunks of 64 (3 x 1024 / 64)

// Scratch (device globals; allocations are forbidden)
__device__ float g_q[SEQ * DIM];
__device__ float g_cos[SEQ * 32];
__device__ float g_sin[SEQ * 32];
__device__ __nv_bfloat16 g_kh[SEQ * DIM], g_kl[SEQ * DIM];
__device__ __nv_bfloat16 g_vh[SEQ * DIM], g_vl[SEQ * DIM];
__device__ __nv_bfloat16 g_abig[SEQ * KS];        // [Ah|Al] for x / att
__device__ __nv_bfloat16 g_wbig[4][DIM * KS];     // [Wh|Wl] per weight

// ===========================================================================
// Helpers (sm_80+ generic)
// ===========================================================================
__device__ __forceinline__ uint32_t smem_u32(const void* p) {
    uint32_t a;
    asm("{ .reg .u64 t; cvta.to.shared.u64 t, %1; cvt.u32.u64 %0, t; }"
        : "=r"(a) : "l"(p));
    return a;
}
__device__ __forceinline__ void ldsm_x4(uint32_t* r, uint32_t addr) {
    asm volatile("ldmatrix.sync.aligned.m8n8.x4.shared.b16 {%0,%1,%2,%3}, [%4];"
                 : "=r"(r[0]), "=r"(r[1]), "=r"(r[2]), "=r"(r[3]) : "r"(addr));
}
__device__ __forceinline__ void ldsm_x4_t(uint32_t* r, uint32_t addr) {
    asm volatile("ldmatrix.sync.aligned.m8n8.x4.trans.shared.b16 {%0,%1,%2,%3}, [%4];"
                 : "=r"(r[0]), "=r"(r[1]), "=r"(r[2]), "=r"(r[3]) : "r"(addr));
}
__device__ __forceinline__ void mma16816(float* d, const uint32_t* a, const uint32_t* b) {
    asm volatile("mma.sync.aligned.m16n8k16.row.col.f32.bf16.bf16.f32 "
                 "{%0,%1,%2,%3}, {%4,%5,%6,%7}, {%8,%9}, {%0,%1,%2,%3};"
                 : "+f"(d[0]), "+f"(d[1]), "+f"(d[2]), "+f"(d[3])
                 : "r"(a[0]), "r"(a[1]), "r"(a[2]), "r"(a[3]),
                   "r"(b[0]), "r"(b[1]));
}
__device__ __forceinline__ void cp_async16(uint32_t dst, const void* src) {
    asm volatile("cp.async.cg.shared.global [%0], [%1], 16;" :: "r"(dst), "l"(src));
}
#define CP_COMMIT() asm volatile("cp.async.commit_group;" ::: "memory")
#define CP_WAIT(n)  asm volatile("cp.async.wait_group %0;" :: "n"(n) : "memory")

__device__ __forceinline__ uint32_t sw128(uint32_t off) {
    return off ^ ((off >> 3) & 0x70);
}
// Packed split: hi = bf16x2(x,y); residual lo via recovered hi floats.
__device__ __forceinline__ uint32_t pack_split(float x, float y, uint32_t* lo) {
    uint32_t hi;
    asm("cvt.rn.bf16x2.f32 %0, %1, %2;" : "=r"(hi) : "f"(y), "f"(x));
    float hfx = __uint_as_float(hi << 16);
    float hfy = __uint_as_float(hi & 0xFFFF0000u);
    float rx = x - hfx, ry = y - hfy;
    uint32_t l;
    asm("cvt.rn.bf16x2.f32 %0, %1, %2;" : "=r"(l) : "f"(ry), "f"(rx));
    *lo = l;
    return hi;
}

// ===========================================================================
// Fused prologue: rope table + x split + 4 weight splits + v1 tail copy.
// ===========================================================================
__global__ __launch_bounds__(256) void prep_kernel(const float* __restrict__ x,
                                                   const float* __restrict__ Wq,
                                                   const float* __restrict__ Wk,
                                                   const float* __restrict__ Wv,
                                                   const float* __restrict__ Wo,
                                                   const float4* __restrict__ v1_4,
                                                   float4* __restrict__ out_tail) {
    int b = blockIdx.x, tid = threadIdx.x;
    if (b < 256) {                              // RoPE table
        int idx = b * 256 + tid;
        int t = idx >> 5, i = idx & 31;
        double p = pow(10000.0, (double)i / 32.0);
        float invf = 1.0f / (float)p;
        float f = (float)t * invf;
        double fd = (double)f;
        g_cos[t * 32 + i] = (float)cos(fd);
        g_sin[t * 32 + i] = (float)sin(fd);
    } else if (b < 1280) {                      // x -> abig [H|L]
        int base = (b - 256) * 512;
#pragma unroll
        for (int i = 0; i < 2; i++) {
            int idx = base + i * 256 + tid;
            int r = idx >> 8, c4 = idx & 255;
            float4 xv = *(const float4*)&x[(size_t)idx * 4];
            uint32_t l0, l1;
            uint32_t h0 = pack_split(xv.x, xv.y, &l0);
            uint32_t h1 = pack_split(xv.z, xv.w, &l1);
            size_t d = (size_t)r * KS + c4 * 4;
            *(uint2*)&g_abig[d] = make_uint2(h0, h1);
            *(uint2*)&g_abig[d + 1024] = make_uint2(l0, l1);
        }
    } else if (b < 3328) {                      // weights -> wbig [H|L]
        int j = b - 1280;
        int wsel = j >> 9;
        const float* src = (wsel == 0) ? Wq : (wsel == 1) ? Wk : (wsel == 2) ? Wv : Wo;
        __nv_bfloat16* d = g_wbig[wsel];
        int base = (j & 511) * 512;
#pragma unroll
        for (int i = 0; i < 2; i++) {
            int idx = base + i * 256 + tid;
            int r = idx >> 8, c4 = idx & 255;
            float4 xv = *(const float4*)&src[(size_t)idx * 4];
            uint32_t l0, l1;
            uint32_t h0 = pack_split(xv.x, xv.y, &l0);
            uint32_t h1 = pack_split(xv.z, xv.w, &l1);
            size_t db = (size_t)r * KS + c4 * 4;
            *(uint2*)&d[db] = make_uint2(h0, h1);
            *(uint2*)&d[db + 1024] = make_uint2(l0, l1);
        }
    } else {                                    // v1 passthrough tail
        int i0 = (b - 3328) * 512 + tid;
        out_tail[i0] = v1_4[i0];
        out_tail[i0 + 256] = v1_4[i0 + 256];
    }
}

// ===========================================================================
// HMMA NT GEMM, 3-term split via chunk remap. CTA 64x128, 4 warps (32x64),
// 2-stage cp.async, 4 CTAs/SM. FUSE=1: fused QKV epilogue (z in {0,1,2}).
// FUSE=0: plain Wout store.
// ===========================================================================
#define TM 64
#define TN 128
#define ASZ (TM * 128)             // 8 KB
#define BSZ (TN * 128)             // 16 KB
#define SSTG (ASZ + BSZ)           // 24 KB per stage
#define GSMEM (2 * SSTG)           // 48 KB

__device__ __forceinline__ void g_load_chunk(uint32_t sb, int st,
                                             const char* Ag, const char* Bg,
                                             int c, int tid) {
    uint32_t ab = sb + st * SSTG;
    uint32_t bb = ab + ASZ;
    int ca = (c < 16) ? c : c - 16;
    int cb = (c < 32) ? c : c - 32;
    size_t aoff = (size_t)ca * 128;
    size_t boff = (size_t)cb * 128;
#pragma unroll
    for (int i = 0; i < 4; i++) {
        int u = tid + i * 128;
        int row = u >> 3, seg = u & 7;
        uint32_t off = row * 128 + seg * 16;
        cp_async16(ab + sw128(off), Ag + (size_t)row * (KS * 2) + aoff + seg * 16);
    }
#pragma unroll
    for (int i = 0; i < 8; i++) {
        int u = tid + i * 128;
        int row = u >> 3, seg = u & 7;
        uint32_t off = row * 128 + seg * 16;
        cp_async16(bb + sw128(off), Bg + (size_t)row * (KS * 2) + boff + seg * 16);
    }
}

template <int FUSE>
__global__ __launch_bounds__(128, 4) void gemm_hmma3(const __nv_bfloat16* __restrict__ A,
                                                     const __nv_bfloat16* __restrict__ Bbase,
                                                     float* __restrict__ C,
                                                     const float* __restrict__ v1,
                                                     const float* __restrict__ lam_p) {
    extern __shared__ __align__(128) char smem[];
    uint32_t sb = smem_u32(smem);
    int z = blockIdx.z;
    const __nv_bfloat16* B = Bbase + (size_t)z * DIM * KS;

    int tid = threadIdx.x;
    int wid = tid >> 5, lane = tid & 31;
    int wm = wid & 1, wn = wid >> 1;
    int bm = blockIdx.y * TM, bn = blockIdx.x * TN;

    const char* Ag = (const char*)(A + (size_t)bm * KS);
    const char* Bg = (const char*)(B + (size_t)bn * KS);

    float acc[2][8][4];
#pragma unroll
    for (int mt = 0; mt < 2; mt++)
#pragma unroll
        for (int nt = 0; nt < 8; nt++)
#pragma unroll
            for (int r = 0; r < 4; r++) acc[mt][nt][r] = 0.f;

    g_load_chunk(sb, 0, Ag, Bg, 0, tid);
    CP_COMMIT();

    int a_row = wm * 32 + (lane & 15);
    int a_kb  = (lane >> 4) * 16;
    int b_row = wn * 64 + (lane & 7) + ((lane >> 4) << 3);
    int b_kb  = ((lane >> 3) & 1) * 16;

    int st = 0;
    for (int c = 0; c < NCH; c++) {
        CP_WAIT(0);
        __syncthreads();
        if (c + 1 < NCH) {
            g_load_chunk(sb, st ^ 1, Ag, Bg, c + 1, tid);
            CP_COMMIT();
        }

        uint32_t abase = sb + st * SSTG;
        uint32_t bbase = abase + ASZ;
#pragma unroll
        for (int ks = 0; ks < 4; ks++) {
            uint32_t af[2][4];
#pragma unroll
            for (int mt = 0; mt < 2; mt++) {
                uint32_t off = (a_row + mt * 16) * 128 + ks * 32 + a_kb;
                ldsm_x4(af[mt], abase + sw128(off));
            }
            uint32_t bfr[4][4];
#pragma unroll
            for (int bt = 0; bt < 4; bt++) {
                uint32_t off = (b_row + bt * 16) * 128 + ks * 32 + b_kb;
                ldsm_x4(bfr[bt], bbase + sw128(off));
            }
#pragma unroll
            for (int mt = 0; mt < 2; mt++)
#pragma unroll
                for (int nt = 0; nt < 8; nt++)
                    mma16816(acc[mt][nt], af[mt], &bfr[nt >> 1][(nt & 1) * 2]);
        }
        st ^= 1;
    }

    int gq = lane >> 2, cp = (lane & 3) * 2;

    if (FUSE == 0) {
#pragma unroll
        for (int mt = 0; mt < 2; mt++) {
#pragma unroll
            for (int nt = 0; nt < 8; nt++) {
                int row = bm + wm * 32 + mt * 16 + gq;
                int col = bn + wn * 64 + nt * 8 + cp;
                *(float2*)&C[(size_t)row * DIM + col] =
                    make_float2(acc[mt][nt][0], acc[mt][nt][1]);
                *(float2*)&C[(size_t)(row + 8) * DIM + col] =
                    make_float2(acc[mt][nt][2], acc[mt][nt][3]);
            }
        }
        return;
    }

    const float eps = 1.1920928955078125e-07f;
    int colbase = bn + wn * 64;

    if (z == 2) {
        float lamv = *lam_p;
#pragma unroll
        for (int mt = 0; mt < 2; mt++) {
#pragma unroll
            for (int half = 0; half < 2; half++) {
                int row = bm + wm * 32 + mt * 16 + gq + half * 8;
#pragma unroll
                for (int nt = 0; nt < 8; nt++) {
                    int col = colbase + nt * 8 + cp;
                    float2 w = *(const float2*)&v1[(size_t)row * DIM + col];
                    float a = (1.f - lamv) * acc[mt][nt][half * 2]     + lamv * w.x;
                    float b = (1.f - lamv) * acc[mt][nt][half * 2 + 1] + lamv * w.y;
                    uint32_t lo, hi = pack_split(a, b, &lo);
                    size_t o = (size_t)row * DIM + col;
                    *(uint32_t*)&g_vh[o] = hi;
                    *(uint32_t*)&g_vl[o] = lo;
                }
            }
        }
        return;
    }

#pragma unroll
    for (int mt = 0; mt < 2; mt++) {
#pragma unroll
        for (int half = 0; half < 2; half++) {
            int row = bm + wm * 32 + mt * 16 + gq + half * 8;
            float ss = 0.f;
#pragma unroll
            for (int nt = 0; nt < 8; nt++) {
                float a = acc[mt][nt][half * 2], b = acc[mt][nt][half * 2 + 1];
                ss += a * a + b * b;
            }
            ss += __shfl_xor_sync(0xffffffffu, ss, 1);
            ss += __shfl_xor_sync(0xffffffffu, ss, 2);
            float mean = ss * (1.f / 64.f) + eps;
            float rn = rsqrtf(mean);
            rn = rn * (1.5f - 0.5f * mean * rn * rn);
#pragma unroll
            for (int nt = 0; nt < 4; nt++) {
                int d0 = nt * 8 + cp;
                float c0 = g_cos[row * 32 + d0],  s0 = g_sin[row * 32 + d0];
                float c1 = g_cos[row * 32 + d0 + 1], s1 = g_sin[row * 32 + d0 + 1];
                float a0 = acc[mt][nt][half * 2] * rn;
                float a1 = acc[mt][nt][half * 2 + 1] * rn;
                float b0 = acc[mt][nt + 4][half * 2] * rn;
                float b1 = acc[mt][nt + 4][half * 2 + 1] * rn;
                float o0 = a0 * c0 + b0 * s0, o1 = a1 * c1 + b1 * s1;
                float p0 = -a0 * s0 + b0 * c0, p1 = -a1 * s1 + b1 * c1;
                size_t ob = (size_t)row * DIM + colbase + d0;
                if (z == 0) {
                    *(float2*)&g_q[ob]      = make_float2(o0, o1);
                    *(float2*)&g_q[ob + 32] = make_float2(p0, p1);
                } else {
                    uint32_t lo, hi = pack_split(o0, o1, &lo);
                    *(uint32_t*)&g_kh[ob] = hi;
                    *(uint32_t*)&g_kl[ob] = lo;
                    hi = pack_split(p0, p1, &lo);
                    *(uint32_t*)&g_kh[ob + 32] = hi;
                    *(uint32_t*)&g_kl[ob + 32] = lo;
                }
            }
        }
    }
}

// ===========================================================================
// Flash attention v6: 128-thread CTAs (64 q rows), 2 CTAs/SM.
// Per-warp compute identical to v5 (warp owns 16 q rows).
// ===========================================================================
#define FSTG 32768          // 4 panels x 8 KB per stage
#define FSMEM (2 * FSTG)

__device__ __forceinline__ void f_load_kv(uint32_t sb, int s, int kt,
                                          int h, int tid) {
    const __nv_bfloat16* srcs[4] = {g_kh, g_kl, g_vh, g_vl};
#pragma unroll
    for (int p = 0; p < 4; p++) {
        uint32_t pb = sb + s * FSTG + p * 8192;
        const char* gp = (const char*)(srcs[p] + (size_t)(kt * 64) * DIM + h * HD);
#pragma unroll
        for (int i = 0; i < 4; i++) {
            int u = tid + i * 128;
            int r = u >> 3, seg = u & 7;
            uint32_t off = r * 128 + seg * 16;
            cp_async16(pb + sw128(off), gp + (size_t)r * (DIM * 2) + seg * 16);
        }
    }
}

__global__ __launch_bounds__(128, 2) void flash_hmma(__nv_bfloat16* __restrict__ abig) {
    extern __shared__ __align__(128) char fsm[];
    uint32_t sb = smem_u32(fsm);

    int h  = blockIdx.x;
    int qt = 31 - (int)blockIdx.y;          // LPT: heavy tiles first
    int q0 = qt * 64;
    int tid = threadIdx.x, w = tid >> 5, lane = tid & 31;
    int g = lane >> 2, t4 = lane & 3;

    // Q fragments: scale by 0.125, split hi/lo
    uint32_t aqh[4][4], aql[4][4];
    {
        int row0 = q0 + w * 16 + g;
#pragma unroll
        for (int ks = 0; ks < 4; ks++) {
            int cb = h * HD + ks * 16 + 2 * t4;
            float2 f[4];
            f[0] = *(const float2*)&g_q[(size_t)row0 * DIM + cb];
            f[1] = *(const float2*)&g_q[(size_t)(row0 + 8) * DIM + cb];
            f[2] = *(const float2*)&g_q[(size_t)row0 * DIM + cb + 8];
            f[3] = *(const float2*)&g_q[(size_t)(row0 + 8) * DIM + cb + 8];
#pragma unroll
            for (int r = 0; r < 4; r++)
                aqh[ks][r] = pack_split(f[r].x * 0.125f, f[r].y * 0.125f, &aql[ks][r]);
        }
    }

    float m0 = -1e30f, m1 = -1e30f, l0 = 0.f, l1 = 0.f;
    float o[8][4];
#pragma unroll
    for (int nt = 0; nt < 8; nt++)
#pragma unroll
        for (int r = 0; r < 4; r++) o[nt][r] = 0.f;

    int nbr = (lane & 7) + ((lane >> 4) << 3);
    int nbk = ((lane >> 3) & 1) * 16;
    int tvr = (lane & 7) + 8 * ((lane >> 3) & 1);
    int tvc = 16 * (lane >> 4);

    f_load_kv(sb, 0, 0, h, tid);
    CP_COMMIT();

    int nkt = qt + 1;
    for (int kt = 0; kt < nkt; kt++) {
        int buf = kt & 1;
        if (kt + 1 < nkt) {
            f_load_kv(sb, buf ^ 1, kt + 1, h, tid);
            CP_COMMIT();
            CP_WAIT(1);
        } else {
            CP_WAIT(0);
        }
        __syncthreads();

        if (kt * 64 <= q0 + w * 16 + 15) {
            uint32_t stg = sb + buf * FSTG;

            float s[8][4];
#pragma unroll
            for (int nt = 0; nt < 8; nt++)
#pragma unroll
                for (int r = 0; r < 4; r++) s[nt][r] = 0.f;

            // --- QK pass 1: K-hi panel, terms qh.KH and ql.KH ---
#pragma unroll
            for (int ks = 0; ks < 4; ks++) {
                uint32_t bfr[4][4];
#pragma unroll
                for (int bt = 0; bt < 4; bt++) {
                    uint32_t off = sw128((uint32_t)((nbr + bt * 16) * 128 + ks * 32 + nbk));
                    ldsm_x4(bfr[bt], stg + off);
                }
#pragma unroll
                for (int nt = 0; nt < 8; nt++)
                    mma16816(s[nt], aqh[ks], &bfr[nt >> 1][(nt & 1) * 2]);
#pragma unroll
                for (int nt = 0; nt < 8; nt++)
                    mma16816(s[nt], aql[ks], &bfr[nt >> 1][(nt & 1) * 2]);
            }
            // --- QK pass 2: K-lo panel, term qh.KL ---
#pragma unroll
            for (int ks = 0; ks < 4; ks++) {
                uint32_t bfr[4][4];
#pragma unroll
                for (int bt = 0; bt < 4; bt++) {
                    uint32_t off = sw128((uint32_t)((nbr + bt * 16) * 128 + ks * 32 + nbk));
                    ldsm_x4(bfr[bt], stg + 8192 + off);
                }
#pragma unroll
                for (int nt = 0; nt < 8; nt++)
                    mma16816(s[nt], aqh[ks], &bfr[nt >> 1][(nt & 1) * 2]);
            }

            if (kt == qt) {                 // diagonal tile
                int r0 = q0 + w * 16 + g, r1 = r0 + 8;
                int c0 = kt * 64 + 2 * t4;
#pragma unroll
                for (int nt = 0; nt < 8; nt++) {
                    int c = c0 + nt * 8;
                    if (c     > r0) s[nt][0] = -1e30f;
                    if (c + 1 > r0) s[nt][1] = -1e30f;
                    if (c     > r1) s[nt][2] = -1e30f;
                    if (c + 1 > r1) s[nt][3] = -1e30f;
                }
            }

            float mx0 = -1e30f, mx1 = -1e30f;
#pragma unroll
            for (int nt = 0; nt < 8; nt++) {
                mx0 = fmaxf(mx0, fmaxf(s[nt][0], s[nt][1]));
                mx1 = fmaxf(mx1, fmaxf(s[nt][2], s[nt][3]));
            }
            mx0 = fmaxf(mx0, __shfl_xor_sync(0xffffffffu, mx0, 1));
            mx0 = fmaxf(mx0, __shfl_xor_sync(0xffffffffu, mx0, 2));
            mx1 = fmaxf(mx1, __shfl_xor_sync(0xffffffffu, mx1, 1));
            mx1 = fmaxf(mx1, __shfl_xor_sync(0xffffffffu, mx1, 2));
            float mn0 = fmaxf(m0, mx0), mn1 = fmaxf(m1, mx1);
            float al0 = __expf(m0 - mn0), al1 = __expf(m1 - mn1);
            float sum0 = 0.f, sum1 = 0.f;
#pragma unroll
            for (int nt = 0; nt < 8; nt++) {
                s[nt][0] = __expf(s[nt][0] - mn0);
                s[nt][1] = __expf(s[nt][1] - mn0);
                s[nt][2] = __expf(s[nt][2] - mn1);
                s[nt][3] = __expf(s[nt][3] - mn1);
                sum0 += s[nt][0] + s[nt][1];
                sum1 += s[nt][2] + s[nt][3];
            }
            sum0 += __shfl_xor_sync(0xffffffffu, sum0, 1);
            sum0 += __shfl_xor_sync(0xffffffffu, sum0, 2);
            sum1 += __shfl_xor_sync(0xffffffffu, sum1, 1);
            sum1 += __shfl_xor_sync(0xffffffffu, sum1, 2);
            l0 = l0 * al0 + sum0;  m0 = mn0;
            l1 = l1 * al1 + sum1;  m1 = mn1;
#pragma unroll
            for (int nt = 0; nt < 8; nt++) {
                o[nt][0] *= al0; o[nt][1] *= al0;
                o[nt][2] *= al1; o[nt][3] *= al1;
            }

            uint32_t ph[4][4], pl[4][4];
#pragma unroll
            for (int j = 0; j < 4; j++) {
                int u0 = 2 * j, u1 = 2 * j + 1;
                ph[j][0] = pack_split(s[u0][0], s[u0][1], &pl[j][0]);
                ph[j][1] = pack_split(s[u0][2], s[u0][3], &pl[j][1]);
                ph[j][2] = pack_split(s[u1][0], s[u1][1], &pl[j][2]);
                ph[j][3] = pack_split(s[u1][2], s[u1][3], &pl[j][3]);
            }

            // --- PV pass 1: V-hi panel, terms ph.VH and pl.VH ---
#pragma unroll
            for (int j = 0; j < 4; j++) {
                uint32_t bv[4][4];
#pragma unroll
                for (int bt = 0; bt < 4; bt++) {
                    uint32_t off = sw128((uint32_t)((j * 16 + tvr) * 128 + bt * 32 + tvc));
                    ldsm_x4_t(bv[bt], stg + 16384 + off);
                }
#pragma unroll
                for (int nt = 0; nt < 8; nt++)
                    mma16816(o[nt], ph[j], &bv[nt >> 1][(nt & 1) * 2]);
#pragma unroll
                for (int nt = 0; nt < 8; nt++)
                    mma16816(o[nt], pl[j], &bv[nt >> 1][(nt & 1) * 2]);
            }
            // --- PV pass 2: V-lo panel, term ph.VL ---
#pragma unroll
            for (int j = 0; j < 4; j++) {
                uint32_t bv[4][4];
#pragma unroll
                for (int bt = 0; bt < 4; bt++) {
                    uint32_t off = sw128((uint32_t)((j * 16 + tvr) * 128 + bt * 32 + tvc));
                    ldsm_x4_t(bv[bt], stg + 24576 + off);
                }
#pragma unroll
                for (int nt = 0; nt < 8; nt++)
                    mma16816(o[nt], ph[j], &bv[nt >> 1][(nt & 1) * 2]);
            }
        }
        __syncthreads();
    }

    // Epilogue: normalize, split to [H|L] directly into abig
    float i0 = 1.f / l0, i1 = 1.f / l1;
    int row0 = q0 + w * 16 + g;
#pragma unroll
    for (int nt = 0; nt < 8; nt++) {
        int col = h * HD + nt * 8 + 2 * t4;
        size_t b0 = (size_t)row0 * KS + col;
        size_t b1 = (size_t)(row0 + 8) * KS + col;
        uint32_t lo, hi;
        hi = pack_split(o[nt][0] * i0, o[nt][1] * i0, &lo);
        *(uint32_t*)&abig[b0] = hi;
        *(uint32_t*)&abig[b0 + 1024] = lo;
        hi = pack_split(o[nt][2] * i1, o[nt][3] * i1, &lo);
        *(uint32_t*)&abig[b1] = hi;
        *(uint32_t*)&abig[b1 + 1024] = lo;
    }
}

// ===========================================================================
extern "C" void kernel_launch(void* const* d_in, const int* in_sizes, int n_in,
                              void* d_out, int out_size) {
    const float* x    = (const float*)d_in[0];
    const float* v1   = (const float*)d_in[1];
    const float* Wq   = (const float*)d_in[2];
    const float* Wk   = (const float*)d_in[3];
    const float* Wv   = (const float*)d_in[4];
    const float* Wout = (const float*)d_in[5];
    const float* lam  = (const float*)d_in[6];
    float* out = (float*)d_out;

    __nv_bfloat16 *abig, *wbig;
    cudaGetSymbolAddress((void**)&abig, g_abig);
    cudaGetSymbolAddress((void**)&wbig, g_wbig);

    static bool attr_set = false;
    if (!attr_set) {
        cudaFuncSetAttribute(gemm_hmma3<0>, cudaFuncAttributeMaxDynamicSharedMemorySize, GSMEM);
        cudaFuncSetAttribute(gemm_hmma3<1>, cudaFuncAttributeMaxDynamicSharedMemorySize, GSMEM);
        cudaFuncSetAttribute(flash_hmma, cudaFuncAttributeMaxDynamicSharedMemorySize, FSMEM);
        attr_set = true;
    }

    // Fused prologue: rope + splits + v1 tail copy
    int copy_blocks = (out_size >= 2 * SEQ * DIM) ? (SEQ * DIM) / 2048 : 0;
    prep_kernel<<<3328 + copy_blocks, 256>>>(x, Wq, Wk, Wv, Wout,
                                             (const float4*)v1,
                                             (float4*)(out + SEQ * DIM));

    // Fused QKV projections + rmsnorm/rope/blend epilogue
    gemm_hmma3<1><<<dim3(DIM / TN, SEQ / TM, 3), 128, GSMEM>>>(
        abig, wbig, nullptr, v1, lam);

    // Flash attention: 64-q-row CTAs, 2 CTAs/SM
    flash_hmma<<<dim3(NH, SEQ / 64), 128, FSMEM>>>(abig);

    // Output projection (plain epilogue)
    gemm_hmma3<0><<<dim3(DIM / TN, SEQ / TM, 1), 128, GSMEM>>>(
        abig, wbig + 3 * (size_t)DIM * KS, out, nullptr, nullptr);
}